// round 14
// baseline (speedup 1.0000x reference)
#include <cuda_runtime.h>
#include <math.h>

#define PI_HALF 1.57079632679489662f
#define NT 64

// ---------------- scratch (pixel-major [N][B]) ----------------
__device__ float g_y0[729 * 128];
__device__ float g_y1[81 * 128];
__device__ float g_y2[9 * 128];

// Per-sample min/max keys, 128B-padded. Identity 0 for max-reduction.
__device__ unsigned g_kx0[128 * 32];
__device__ unsigned g_kn0[128 * 32];
__device__ unsigned g_kx1[128 * 32];
__device__ unsigned g_kn1[128 * 32];

// ---------------- software grid barrier (self-resetting) ----------------
__device__ unsigned g_count = 0;
__device__ unsigned g_gen = 0;

__device__ __forceinline__ void grid_barrier()
{
    __threadfence();
    __syncthreads();
    if (threadIdx.x == 0) {
        volatile unsigned* gen = &g_gen;
        const unsigned target = *gen + 1;
        const unsigned arrived = atomicAdd(&g_count, 1) + 1;
        if (arrived == gridDim.x) {
            g_count = 0;
            __threadfence();
            atomicAdd(&g_gen, 1);
        } else {
            while ((int)(*gen - target) < 0) __nanosleep(32);
        }
        __threadfence();
    }
    __syncthreads();
}

// ---------------- monotonic float<->uint key ----------------
__device__ __forceinline__ unsigned fkey(float f)
{
    unsigned u = __float_as_uint(f);
    return u ^ ((unsigned)((int)u >> 31) | 0x80000000u);
}
__device__ __forceinline__ float funkey(unsigned k)
{
    unsigned u = (k & 0x80000000u) ? (k ^ 0x80000000u) : ~k;
    return __uint_as_float(u);
}

__device__ __forceinline__ void red_max(unsigned* p, unsigned v)
{
    asm volatile("red.global.max.u32 [%0], %1;" :: "l"(p), "r"(v) : "memory");
}

// ---------------- packed f32x2 FMA ----------------
__device__ __forceinline__ float2 ffma2(float2 a, float2 b, float2 c)
{
    unsigned long long au = *reinterpret_cast<unsigned long long*>(&a);
    unsigned long long bu = *reinterpret_cast<unsigned long long*>(&b);
    unsigned long long cu = *reinterpret_cast<unsigned long long*>(&c);
    unsigned long long du;
    asm("fma.rn.f32x2 %0, %1, %2, %3;" : "=l"(du) : "l"(au), "l"(bu), "l"(cu));
    return *reinterpret_cast<float2*>(&du);
}

// ---------------- cp.async helpers ----------------
__device__ __forceinline__ void cp_async16(float* sdst, const float* gsrc)
{
    unsigned saddr = (unsigned)__cvta_generic_to_shared(sdst);
    asm volatile("cp.async.cg.shared.global [%0], [%1], 16;" :: "r"(saddr), "l"(gsrc));
}
#define CP_COMMIT() asm volatile("cp.async.commit_group;" ::: "memory")
#define CP_WAIT0()  asm volatile("cp.async.wait_group 0;" ::: "memory")

// Permute: (s,a,p,c) -> s*200 + a*20 + (c/2)*4 + (c%2)*2 + p.
// Each (s,a) row = 5 aligned float4s of (p0,p1) c-pairs.
__device__ __forceinline__ int wm_perm(int t)
{
    const int s  = t / 200;
    const int r  = t - s * 200;
    const int a  = r / 20;
    const int r2 = r - a * 20;
    const int p  = r2 / 10;
    const int c  = r2 - p * 10;
    return s * 200 + a * 20 + ((c >> 1) << 2) + ((c & 1) << 1) + p;
}

__device__ __forceinline__ void stage_wm_g(const float* __restrict__ gWm,
                                           float* __restrict__ sWm, int tid)
{
    #pragma unroll
    for (int t = tid; t < 1400; t += NT) sWm[wm_perm(t)] = gWm[t];
}
__device__ __forceinline__ void stage_wm_s(const float* __restrict__ sRaw,
                                           float* __restrict__ sWm, int tid)
{
    #pragma unroll
    for (int t = tid; t < 1400; t += NT) sWm[wm_perm(t)] = sRaw[t];
}

// ---------------- two-sample MPS core, features in smem ----------------
// Thread owns samples b0, b1; features at sX[k*128 + b]. Each LDS.128 weight
// load feeds 4 FFMA2 (2 samples x 2 acc halves): LDS issue-slots per sample
// halve vs the 1-sample core; the two chains give ILP for latency hiding.
__device__ __forceinline__ void mps_core2(const float* __restrict__ fp0,
                                          const float* __restrict__ fp1,
                                          const float* __restrict__ w0c,
                                          const float* __restrict__ w0s,
                                          const float* __restrict__ sWm,
                                          const float* __restrict__ sWn,
                                          float& r0, float& r1)
{
    float c0, s0, c1, s1;
    __sincosf(fp0[0] * PI_HALF, &s0, &c0);
    __sincosf(fp1[0] * PI_HALF, &s1, &c1);
    float v0[10], v1[10];
    #pragma unroll
    for (int a = 0; a < 10; a++) {
        v0[a] = fmaf(s0, w0s[a], c0 * w0c[a]);
        v1[a] = fmaf(s1, w0s[a], c1 * w0c[a]);
    }

    #pragma unroll
    for (int s = 0; s < 7; s++) {
        float cn0, sn0, cn1, sn1;          // MUFU overlapped with the a-loop
        __sincosf(fp0[(s + 1) * 128] * PI_HALF, &sn0, &cn0);
        __sincosf(fp1[(s + 1) * 128] * PI_HALF, &sn1, &cn1);

        const float4* M = reinterpret_cast<const float4*>(sWm + s * 200);
        float2 A0[10], A1[10];
        #pragma unroll
        for (int c = 0; c < 10; c++) { A0[c] = make_float2(0.f, 0.f); A1[c] = make_float2(0.f, 0.f); }
        #pragma unroll
        for (int a = 0; a < 10; a++) {
            const float2 va0 = make_float2(v0[a], v0[a]);
            const float2 va1 = make_float2(v1[a], v1[a]);
            const float4* Ma = M + a * 5;
            #pragma unroll
            for (int j = 0; j < 5; j++) {
                const float4 m = Ma[j];             // one LDS.128 -> 4 FFMA2
                const float2 mlo = make_float2(m.x, m.y);
                const float2 mhi = make_float2(m.z, m.w);
                A0[2 * j]     = ffma2(va0, mlo, A0[2 * j]);
                A0[2 * j + 1] = ffma2(va0, mhi, A0[2 * j + 1]);
                A1[2 * j]     = ffma2(va1, mlo, A1[2 * j]);
                A1[2 * j + 1] = ffma2(va1, mhi, A1[2 * j + 1]);
            }
        }
        #pragma unroll
        for (int c = 0; c < 10; c++) {
            v0[c] = fmaf(sn0, A0[c].y, cn0 * A0[c].x);
            v1[c] = fmaf(sn1, A1[c].y, cn1 * A1[c].x);
        }
    }

    float ce0, se0, ce1, se1;
    __sincosf(fp0[8 * 128] * PI_HALF, &se0, &ce0);
    __sincosf(fp1[8 * 128] * PI_HALF, &se1, &ce1);
    float a0 = 0.f, a1 = 0.f;
    #pragma unroll
    for (int a = 0; a < 10; a++) {
        const float rr = fmaf(se0, sWn[2 * a + 1], ce0 * sWn[2 * a]);
        const float rr1 = fmaf(se1, sWn[2 * a + 1], ce1 * sWn[2 * a]);
        a0 = fmaf(v0[a], rr, a0);
        a1 = fmaf(v1[a], rr1, a1);
    }
    r0 = a0; r1 = a1;
}

// ---------------- single fused kernel ----------------
// NT=64, launch_bounds(64,7): 146-reg cap (no spill expected), grid 7*SMs
// (=1036) -> single-wave phase 0 with one pixel per block, 2 samples/thread.
__global__ void __launch_bounds__(NT, 7)
fused_lotenet(const float* __restrict__ x,
              const float* __restrict__ W00, const float* __restrict__ Wm0, const float* __restrict__ Wn0,
              const float* __restrict__ W01, const float* __restrict__ Wm1, const float* __restrict__ Wn1,
              const float* __restrict__ W02, const float* __restrict__ Wm2, const float* __restrict__ Wn2,
              const float* __restrict__ W03, const float* __restrict__ Wm3, const float* __restrict__ Wn3,
              float* __restrict__ out)
{
    __shared__ __align__(16) float sWm[1400];
    __shared__ __align__(16) float sRaw[1664];
    __shared__ __align__(16) float sX[9 * 128];
    __shared__ __align__(16) float sW0[200];
    __shared__ float sWn[20];

    const int tid = threadIdx.x;
    const int bid = blockIdx.x;
    const int nblk = gridDim.x;

    const int b0 = tid, b1 = tid + 64;

    // ---- Phase 0: layer-0 MPS, one pixel per block (single wave) ----
    for (int n = bid; n < 729; n += nblk) {
        __syncthreads();
        stage_wm_g(Wm0 + n * 1400, sWm, tid);
        if (tid < 20)      sW0[tid]      = W00[n * 20 + tid];
        else if (tid < 40) sWn[tid - 20] = Wn0[n * 20 + (tid - 20)];
        const int i = n / 27, j = n - i * 27;
        #pragma unroll
        for (int k = 0; k < 9; k++) {
            const int r = 3 * i + k / 3;
            const int c = 3 * j + (k - (k / 3) * 3);
            sX[k * 128 + b0] = x[((size_t)b0 * 81 + r) * 81 + c];
            sX[k * 128 + b1] = x[((size_t)b1 * 81 + r) * 81 + c];
        }
        __syncthreads();

        float y0v, y1v;
        mps_core2(sX + b0, sX + b1, sW0, sW0 + 10, sWm, sWn, y0v, y1v);
        g_y0[n * 128 + b0] = y0v;
        g_y0[n * 128 + b1] = y1v;
        red_max(&g_kx0[b0 * 32], fkey(y0v));
        red_max(&g_kn0[b0 * 32], ~fkey(y0v));
        red_max(&g_kx0[b1 * 32], fkey(y1v));
        red_max(&g_kn0[b1 * 32], ~fkey(y1v));
    }

    // Prefetch phase-1 weights; copies land while we spin in the barrier.
    if (bid < 81) {
        const float* gWm = Wm1 + bid * 1400;
        const float* gW0 = W01 + bid * 20;
        const float* gWn = Wn1 + bid * 20;
        #pragma unroll
        for (int t = tid; t < 360; t += NT) {
            if (t < 350)      cp_async16(sRaw + t * 4,                gWm + t * 4);
            else if (t < 355) cp_async16(sRaw + 1400 + (t - 350) * 4, gW0 + (t - 350) * 4);
            else              cp_async16(sRaw + 1420 + (t - 355) * 4, gWn + (t - 355) * 4);
        }
        CP_COMMIT();
    }
    grid_barrier();

    // ---- Phase 1: layer-1 MPS, 81 blocks ----
    if (bid < 81) {
        CP_WAIT0();
        __syncthreads();
        stage_wm_s(sRaw, sWm, tid);
        if (tid < 20)      sW0[tid]      = sRaw[1400 + tid];
        else if (tid < 40) sWn[tid - 20] = sRaw[1420 + (tid - 20)];

        const float mn0 = funkey(~g_kn0[b0 * 32]);
        const float iv0 = 1.0f / (funkey(g_kx0[b0 * 32]) - mn0);
        const float mn1 = funkey(~g_kn0[b1 * 32]);
        const float iv1 = 1.0f / (funkey(g_kx0[b1 * 32]) - mn1);

        const int n = bid;
        const int i = n / 9, j = n - i * 9;
        #pragma unroll
        for (int k = 0; k < 9; k++) {
            const int r = 3 * i + k / 3;
            const int c = 3 * j + (k - (k / 3) * 3);
            sX[k * 128 + b0] = (g_y0[(r * 27 + c) * 128 + b0] - mn0) * iv0;
            sX[k * 128 + b1] = (g_y0[(r * 27 + c) * 128 + b1] - mn1) * iv1;
        }
        __syncthreads();

        float y0v, y1v;
        mps_core2(sX + b0, sX + b1, sW0, sW0 + 10, sWm, sWn, y0v, y1v);
        g_y1[n * 128 + b0] = y0v;
        g_y1[n * 128 + b1] = y1v;
        red_max(&g_kx1[b0 * 32], fkey(y0v));
        red_max(&g_kn1[b0 * 32], ~fkey(y0v));
        red_max(&g_kx1[b1 * 32], fkey(y1v));
        red_max(&g_kn1[b1 * 32], ~fkey(y1v));

        // Prefetch phase-2 weights (blocks 0..8).
        if (bid < 9) {
            __syncthreads();
            const float* gWm = Wm2 + bid * 1400;
            const float* gW0 = W02 + bid * 20;
            const float* gWn = Wn2 + bid * 20;
            #pragma unroll
            for (int t = tid; t < 360; t += NT) {
                if (t < 350)      cp_async16(sRaw + t * 4,                gWm + t * 4);
                else if (t < 355) cp_async16(sRaw + 1400 + (t - 350) * 4, gW0 + (t - 350) * 4);
                else              cp_async16(sRaw + 1420 + (t - 355) * 4, gWn + (t - 355) * 4);
            }
            CP_COMMIT();
        }
    }
    grid_barrier();

    // ---- Phase 2: layer-2 MPS, 9 blocks. Last block resets L0 keys. ----
    if (bid < 9) {
        CP_WAIT0();
        __syncthreads();
        stage_wm_s(sRaw, sWm, tid);
        if (tid < 20)      sW0[tid]      = sRaw[1400 + tid];
        else if (tid < 40) sWn[tid - 20] = sRaw[1420 + (tid - 20)];

        const float mn0 = funkey(~g_kn1[b0 * 32]);
        const float iv0 = 1.0f / (funkey(g_kx1[b0 * 32]) - mn0);
        const float mn1 = funkey(~g_kn1[b1 * 32]);
        const float iv1 = 1.0f / (funkey(g_kx1[b1 * 32]) - mn1);

        const int n = bid;
        const int i = n / 3, j = n - i * 3;
        #pragma unroll
        for (int k = 0; k < 9; k++) {
            const int r = 3 * i + k / 3;
            const int c = 3 * j + (k - (k / 3) * 3);
            sX[k * 128 + b0] = (g_y1[(r * 9 + c) * 128 + b0] - mn0) * iv0;
            sX[k * 128 + b1] = (g_y1[(r * 9 + c) * 128 + b1] - mn1) * iv1;
        }
        __syncthreads();

        float y0v, y1v;
        mps_core2(sX + b0, sX + b1, sW0, sW0 + 10, sWm, sWn, y0v, y1v);
        g_y2[n * 128 + b0] = y0v;
        g_y2[n * 128 + b1] = y1v;
    } else if (bid == nblk - 1) {
        g_kx0[tid * 32] = 0;        g_kn0[tid * 32] = 0;
        g_kx0[(tid + 64) * 32] = 0; g_kn0[(tid + 64) * 32] = 0;
    }
    // Prefetch final-layer weights (blocks 0..9).
    if (bid < 10) {
        if (bid < 9) __syncthreads();
        #pragma unroll
        for (int t = tid; t < 405; t += NT) {
            if (t < 350)      cp_async16(sRaw + t * 4,                Wm3 + t * 4);
            else if (t < 400) cp_async16(sRaw + 1400 + (t - 350) * 4, W03 + (t - 350) * 4);
            else              cp_async16(sRaw + 1600 + (t - 400) * 4, Wn3 + (t - 400) * 4);
        }
        CP_COMMIT();
    }
    grid_barrier();

    // ---- Phase 3: final MPS (O=10), 10 blocks. Last block resets L1 keys. ----
    if (bid < 10) {
        CP_WAIT0();
        __syncthreads();
        stage_wm_s(sRaw, sWm, tid);
        #pragma unroll
        for (int t = tid; t < 200; t += NT) sW0[t] = sRaw[1400 + t];
        if (tid < 20) sWn[tid] = sRaw[1600 + tid];

        float mn0 = INFINITY, mx0 = -INFINITY, mn1 = INFINITY, mx1 = -INFINITY;
        #pragma unroll
        for (int k = 0; k < 9; k++) {
            const float u0 = g_y2[k * 128 + b0];
            const float u1 = g_y2[k * 128 + b1];
            sX[k * 128 + b0] = u0;
            sX[k * 128 + b1] = u1;
            mn0 = fminf(mn0, u0);  mx0 = fmaxf(mx0, u0);
            mn1 = fminf(mn1, u1);  mx1 = fmaxf(mx1, u1);
        }
        const float iv0 = 1.0f / (mx0 - mn0);
        const float iv1 = 1.0f / (mx1 - mn1);
        #pragma unroll
        for (int k = 0; k < 9; k++) {
            sX[k * 128 + b0] = (sX[k * 128 + b0] - mn0) * iv0;
            sX[k * 128 + b1] = (sX[k * 128 + b1] - mn1) * iv1;
        }
        __syncthreads();

        const int o = bid;
        float y0v, y1v;
        mps_core2(sX + b0, sX + b1, sW0 + o * 10, sW0 + 100 + o * 10, sWm, sWn, y0v, y1v);
        out[b0 * 10 + o] = y0v;
        out[b1 * 10 + o] = y1v;
    } else if (bid == nblk - 1) {
        g_kx1[tid * 32] = 0;        g_kn1[tid * 32] = 0;
        g_kx1[(tid + 64) * 32] = 0; g_kn1[(tid + 64) * 32] = 0;
    }
}

extern "C" void kernel_launch(void* const* d_in, const int* in_sizes, int n_in,
                              void* d_out, int out_size)
{
    const float* x   = (const float*)d_in[0];
    const float* W00 = (const float*)d_in[1];
    const float* Wm0 = (const float*)d_in[2];
    const float* Wn0 = (const float*)d_in[3];
    const float* W01 = (const float*)d_in[6];
    const float* Wm1 = (const float*)d_in[7];
    const float* Wn1 = (const float*)d_in[8];
    const float* W02 = (const float*)d_in[11];
    const float* Wm2 = (const float*)d_in[12];
    const float* Wn2 = (const float*)d_in[13];
    const float* W03 = (const float*)d_in[16];
    const float* Wm3 = (const float*)d_in[17];
    const float* Wn3 = (const float*)d_in[18];

    int nsm = 148;
    cudaDeviceGetAttribute(&nsm, cudaDevAttrMultiProcessorCount, 0);
    const int grid = 7 * nsm;   // __launch_bounds__(64,7): all resident, >=729

    fused_lotenet<<<grid, NT>>>(x, W00, Wm0, Wn0, W01, Wm1, Wn1,
                                W02, Wm2, Wn2, W03, Wm3, Wn3,
                                (float*)d_out);
}

// round 15
// speedup vs baseline: 1.5342x; 1.5342x over previous
#include <cuda_runtime.h>
#include <math.h>

#define PI_HALF 1.57079632679489662f
#define NT 128

// ---------------- scratch (pixel-major [N][B]) ----------------
__device__ float g_y0[729 * 128];
__device__ float g_y1[81 * 128];
__device__ float g_y2[9 * 128];

// Per-sample min/max atomic keys, 128B-padded. Identity 0 for atomicMax.
__device__ unsigned g_kx0[128 * 32];
__device__ unsigned g_kn0[128 * 32];
__device__ unsigned g_kx1[128 * 32];
__device__ unsigned g_kn1[128 * 32];

// ---------------- software grid barrier (self-resetting) ----------------
__device__ unsigned g_count = 0;
__device__ unsigned g_gen = 0;

__device__ __forceinline__ void grid_barrier()
{
    __threadfence();
    __syncthreads();
    if (threadIdx.x == 0) {
        volatile unsigned* gen = &g_gen;
        const unsigned target = *gen + 1;
        const unsigned arrived = atomicAdd(&g_count, 1) + 1;
        if (arrived == gridDim.x) {
            g_count = 0;
            __threadfence();
            atomicAdd(&g_gen, 1);
        } else {
            while ((int)(*gen - target) < 0) __nanosleep(32);
        }
        __threadfence();
    }
    __syncthreads();
}

// ---------------- monotonic float<->uint key ----------------
__device__ __forceinline__ unsigned fkey(float f)
{
    unsigned u = __float_as_uint(f);
    return u ^ ((unsigned)((int)u >> 31) | 0x80000000u);
}
__device__ __forceinline__ float funkey(unsigned k)
{
    unsigned u = (k & 0x80000000u) ? (k ^ 0x80000000u) : ~k;
    return __uint_as_float(u);
}

// ---------------- packed f32x2 FMA ----------------
__device__ __forceinline__ float2 ffma2(float2 a, float2 b, float2 c)
{
    unsigned long long au = *reinterpret_cast<unsigned long long*>(&a);
    unsigned long long bu = *reinterpret_cast<unsigned long long*>(&b);
    unsigned long long cu = *reinterpret_cast<unsigned long long*>(&c);
    unsigned long long du;
    asm("fma.rn.f32x2 %0, %1, %2, %3;" : "=l"(du) : "l"(au), "l"(bu), "l"(cu));
    return *reinterpret_cast<float2*>(&du);
}

// ---------------- cp.async helpers ----------------
__device__ __forceinline__ void cp_async16(float* sdst, const float* gsrc)
{
    unsigned saddr = (unsigned)__cvta_generic_to_shared(sdst);
    asm volatile("cp.async.cg.shared.global [%0], [%1], 16;" :: "r"(saddr), "l"(gsrc));
}
#define CP_COMMIT() asm volatile("cp.async.commit_group;" ::: "memory")
#define CP_WAIT0()  asm volatile("cp.async.wait_group 0;" ::: "memory")

// Permute: (s,a,p,c) -> s*200 + a*20 + (c/2)*4 + (c%2)*2 + p.
// Each (s,a) row = 5 aligned float4s of (p0,p1) c-pairs.
__device__ __forceinline__ int wm_perm(int t)
{
    const int s  = t / 200;
    const int r  = t - s * 200;
    const int a  = r / 20;
    const int r2 = r - a * 20;
    const int p  = r2 / 10;
    const int c  = r2 - p * 10;
    return s * 200 + a * 20 + ((c >> 1) << 2) + ((c & 1) << 1) + p;
}

__device__ __forceinline__ void stage_wm_g(const float* __restrict__ gWm,
                                           float* __restrict__ sWm, int tid)
{
    #pragma unroll
    for (int t = tid; t < 1400; t += NT) sWm[wm_perm(t)] = gWm[t];
}
__device__ __forceinline__ void stage_wm_s(const float* __restrict__ sRaw,
                                           float* __restrict__ sWm, int tid)
{
    #pragma unroll
    for (int t = tid; t < 1400; t += NT) sWm[wm_perm(t)] = sRaw[t];
}

// ---------------- single-sample MPS core, features in smem ----------------
// fp points at this thread's feature column: feature k at fp[k*128].
// Keeping features in smem (private column, no syncs needed) frees ~10
// registers vs the register-resident f[9], letting the kernel fit the
// 85-reg cap of launch_bounds(128,6) without spilling the hot loop.
__device__ __forceinline__ float mps_core(const float* __restrict__ fp,
                                          const float* __restrict__ w0c,
                                          const float* __restrict__ w0s,
                                          const float* __restrict__ sWm,
                                          const float* __restrict__ sWn)
{
    float c0, s0;
    __sincosf(fp[0] * PI_HALF, &s0, &c0);
    float v[10];
    #pragma unroll
    for (int a = 0; a < 10; a++)
        v[a] = fmaf(s0, w0s[a], c0 * w0c[a]);

    #pragma unroll
    for (int s = 0; s < 7; s++) {
        float cn, sn;                      // MUFU overlapped with the a-loop
        __sincosf(fp[(s + 1) * 128] * PI_HALF, &sn, &cn);
        const float4* M = reinterpret_cast<const float4*>(sWm + s * 200);
        float2 acc[10];
        #pragma unroll
        for (int c = 0; c < 10; c++) acc[c] = make_float2(0.f, 0.f);
        #pragma unroll
        for (int a = 0; a < 10; a++) {
            const float2 va2 = make_float2(v[a], v[a]);
            const float4* Ma = M + a * 5;
            #pragma unroll
            for (int j = 0; j < 5; j++) {
                const float4 m = Ma[j];    // one LDS.128 -> 2 FFMA2
                acc[2 * j]     = ffma2(va2, make_float2(m.x, m.y), acc[2 * j]);
                acc[2 * j + 1] = ffma2(va2, make_float2(m.z, m.w), acc[2 * j + 1]);
            }
        }
        #pragma unroll
        for (int c = 0; c < 10; c++)
            v[c] = fmaf(sn, acc[c].y, cn * acc[c].x);
    }

    float ce, se;
    __sincosf(fp[8 * 128] * PI_HALF, &se, &ce);
    float r = 0.f;
    #pragma unroll
    for (int a = 0; a < 10; a++)
        r = fmaf(v[a], fmaf(se, sWn[2 * a + 1], ce * sWn[2 * a]), r);
    return r;
}

// ---------------- single fused kernel ----------------
// launch_bounds(128,6): 85-reg cap, 6 resident blocks/SM -> grid 6*SMs (=888)
// single-wave phase 0 with 24 warps/SM; barrier residency-safe.
__global__ void __launch_bounds__(NT, 6)
fused_lotenet(const float* __restrict__ x,
              const float* __restrict__ W00, const float* __restrict__ Wm0, const float* __restrict__ Wn0,
              const float* __restrict__ W01, const float* __restrict__ Wm1, const float* __restrict__ Wn1,
              const float* __restrict__ W02, const float* __restrict__ Wm2, const float* __restrict__ Wn2,
              const float* __restrict__ W03, const float* __restrict__ Wm3, const float* __restrict__ Wn3,
              float* __restrict__ out)
{
    __shared__ __align__(16) float sWm[1400];
    __shared__ __align__(16) float sRaw[1664];
    __shared__ __align__(16) float sX[9 * 128];   // per-thread feature columns
    __shared__ __align__(16) float sW0[200];
    __shared__ float sWn[20];

    const int tid = threadIdx.x;   // sample b
    const int bid = blockIdx.x;
    const int nblk = gridDim.x;

    const float* fp = sX + tid;    // this thread's feature column

    // ---- Phase 0: layer-0 MPS, one pixel per block (single wave) ----
    for (int n = bid; n < 729; n += nblk) {
        __syncthreads();
        stage_wm_g(Wm0 + n * 1400, sWm, tid);
        if (tid < 20)      sW0[tid]      = W00[n * 20 + tid];
        else if (tid < 40) sWn[tid - 20] = Wn0[n * 20 + (tid - 20)];

        const int i = n / 27, j = n - i * 27;
        #pragma unroll
        for (int k = 0; k < 9; k++) {
            const int r = 3 * i + k / 3;
            const int c = 3 * j + (k - (k / 3) * 3);
            sX[k * 128 + tid] = x[((size_t)tid * 81 + r) * 81 + c];
        }
        __syncthreads();

        const float y = mps_core(fp, sW0, sW0 + 10, sWm, sWn);
        g_y0[n * 128 + tid] = y;
        atomicMax(&g_kx0[tid * 32], fkey(y));
        atomicMax(&g_kn0[tid * 32], ~fkey(y));
    }

    // Prefetch phase-1 weights; copies land while we spin in the barrier.
    if (bid < 81) {
        const float* gWm = Wm1 + bid * 1400;
        const float* gW0 = W01 + bid * 20;
        const float* gWn = Wn1 + bid * 20;
        #pragma unroll
        for (int t = tid; t < 360; t += NT) {
            if (t < 350)      cp_async16(sRaw + t * 4,                gWm + t * 4);
            else if (t < 355) cp_async16(sRaw + 1400 + (t - 350) * 4, gW0 + (t - 350) * 4);
            else              cp_async16(sRaw + 1420 + (t - 355) * 4, gWn + (t - 355) * 4);
        }
        CP_COMMIT();
    }
    grid_barrier();

    // ---- Phase 1: layer-1 MPS, 81 blocks ----
    if (bid < 81) {
        CP_WAIT0();
        __syncthreads();
        stage_wm_s(sRaw, sWm, tid);
        if (tid < 20)      sW0[tid]      = sRaw[1400 + tid];
        else if (tid < 40) sWn[tid - 20] = sRaw[1420 + (tid - 20)];

        const float mn = funkey(~g_kn0[tid * 32]);
        const float iv = 1.0f / (funkey(g_kx0[tid * 32]) - mn);

        const int n = bid;
        const int i = n / 9, j = n - i * 9;
        #pragma unroll
        for (int k = 0; k < 9; k++) {
            const int r = 3 * i + k / 3;
            const int c = 3 * j + (k - (k / 3) * 3);
            sX[k * 128 + tid] = (g_y0[(r * 27 + c) * 128 + tid] - mn) * iv;
        }
        __syncthreads();

        const float y = mps_core(fp, sW0, sW0 + 10, sWm, sWn);
        g_y1[n * 128 + tid] = y;
        atomicMax(&g_kx1[tid * 32], fkey(y));
        atomicMax(&g_kn1[tid * 32], ~fkey(y));

        // Prefetch phase-2 weights (blocks 0..8).
        if (bid < 9) {
            __syncthreads();
            const float* gWm = Wm2 + bid * 1400;
            const float* gW0 = W02 + bid * 20;
            const float* gWn = Wn2 + bid * 20;
            #pragma unroll
            for (int t = tid; t < 360; t += NT) {
                if (t < 350)      cp_async16(sRaw + t * 4,                gWm + t * 4);
                else if (t < 355) cp_async16(sRaw + 1400 + (t - 350) * 4, gW0 + (t - 350) * 4);
                else              cp_async16(sRaw + 1420 + (t - 355) * 4, gWn + (t - 355) * 4);
            }
            CP_COMMIT();
        }
    }
    grid_barrier();

    // ---- Phase 2: layer-2 MPS, 9 blocks. Last block resets L0 keys. ----
    if (bid < 9) {
        CP_WAIT0();
        __syncthreads();
        stage_wm_s(sRaw, sWm, tid);
        if (tid < 20)      sW0[tid]      = sRaw[1400 + tid];
        else if (tid < 40) sWn[tid - 20] = sRaw[1420 + (tid - 20)];

        const float mn = funkey(~g_kn1[tid * 32]);
        const float iv = 1.0f / (funkey(g_kx1[tid * 32]) - mn);

        const int n = bid;
        const int i = n / 3, j = n - i * 3;
        #pragma unroll
        for (int k = 0; k < 9; k++) {
            const int r = 3 * i + k / 3;
            const int c = 3 * j + (k - (k / 3) * 3);
            sX[k * 128 + tid] = (g_y1[(r * 9 + c) * 128 + tid] - mn) * iv;
        }
        __syncthreads();

        g_y2[n * 128 + tid] = mps_core(fp, sW0, sW0 + 10, sWm, sWn);
    } else if (bid == nblk - 1) {
        g_kx0[tid * 32] = 0;
        g_kn0[tid * 32] = 0;
    }
    // Prefetch final-layer weights (blocks 0..9).
    if (bid < 10) {
        if (bid < 9) __syncthreads();
        #pragma unroll
        for (int t = tid; t < 405; t += NT) {
            if (t < 350)      cp_async16(sRaw + t * 4,                Wm3 + t * 4);
            else if (t < 400) cp_async16(sRaw + 1400 + (t - 350) * 4, W03 + (t - 350) * 4);
            else              cp_async16(sRaw + 1600 + (t - 400) * 4, Wn3 + (t - 400) * 4);
        }
        CP_COMMIT();
    }
    grid_barrier();

    // ---- Phase 3: final MPS (O=10), 10 blocks. Last block resets L1 keys. ----
    if (bid < 10) {
        CP_WAIT0();
        __syncthreads();
        stage_wm_s(sRaw, sWm, tid);
        #pragma unroll
        for (int t = tid; t < 200; t += NT) sW0[t] = sRaw[1400 + t];
        if (tid < 20) sWn[tid] = sRaw[1600 + tid];

        float mn = INFINITY, mx = -INFINITY;
        #pragma unroll
        for (int k = 0; k < 9; k++) {
            const float u = g_y2[k * 128 + tid];
            sX[k * 128 + tid] = u;
            mn = fminf(mn, u);
            mx = fmaxf(mx, u);
        }
        const float iv = 1.0f / (mx - mn);
        #pragma unroll
        for (int k = 0; k < 9; k++)
            sX[k * 128 + tid] = (sX[k * 128 + tid] - mn) * iv;
        __syncthreads();

        const int o = bid;
        out[tid * 10 + o] = mps_core(fp, sW0 + o * 10, sW0 + 100 + o * 10, sWm, sWn);
    } else if (bid == nblk - 1) {
        g_kx1[tid * 32] = 0;
        g_kn1[tid * 32] = 0;
    }
}

extern "C" void kernel_launch(void* const* d_in, const int* in_sizes, int n_in,
                              void* d_out, int out_size)
{
    const float* x   = (const float*)d_in[0];
    const float* W00 = (const float*)d_in[1];
    const float* Wm0 = (const float*)d_in[2];
    const float* Wn0 = (const float*)d_in[3];
    const float* W01 = (const float*)d_in[6];
    const float* Wm1 = (const float*)d_in[7];
    const float* Wn1 = (const float*)d_in[8];
    const float* W02 = (const float*)d_in[11];
    const float* Wm2 = (const float*)d_in[12];
    const float* Wn2 = (const float*)d_in[13];
    const float* W03 = (const float*)d_in[16];
    const float* Wm3 = (const float*)d_in[17];
    const float* Wn3 = (const float*)d_in[18];

    int nsm = 148;
    cudaDeviceGetAttribute(&nsm, cudaDevAttrMultiProcessorCount, 0);
    const int grid = 6 * nsm;   // __launch_bounds__(128,6): all resident

    fused_lotenet<<<grid, NT>>>(x, W00, Wm0, Wn0, W01, Wm1, Wn1,
                                W02, Wm2, Wn2, W03, Wm3, Wn3,
                                (float*)d_out);
}

// round 16
// speedup vs baseline: 1.6266x; 1.0602x over previous
#include <cuda_runtime.h>
#include <math.h>

#define PI_HALF 1.57079632679489662f
#define NT 128

// ---------------- scratch (pixel-major [N][B]) ----------------
__device__ float g_y0[729 * 128];
__device__ float g_y1[81 * 128];
__device__ float g_y2[9 * 128];

// Per-sample min/max atomic keys, 128B-padded. Identity 0 for atomicMax.
__device__ unsigned g_kx0[128 * 32];
__device__ unsigned g_kn0[128 * 32];
__device__ unsigned g_kx1[128 * 32];
__device__ unsigned g_kn1[128 * 32];

// ---------------- software grid barrier (self-resetting) ----------------
__device__ unsigned g_count = 0;
__device__ unsigned g_gen = 0;

__device__ __forceinline__ void grid_barrier()
{
    __threadfence();
    __syncthreads();
    if (threadIdx.x == 0) {
        volatile unsigned* gen = &g_gen;
        const unsigned target = *gen + 1;
        const unsigned arrived = atomicAdd(&g_count, 1) + 1;
        if (arrived == gridDim.x) {
            g_count = 0;
            __threadfence();
            atomicAdd(&g_gen, 1);
        } else {
            while ((int)(*gen - target) < 0) __nanosleep(32);
        }
        __threadfence();
    }
    __syncthreads();
}

// ---------------- monotonic float<->uint key ----------------
__device__ __forceinline__ unsigned fkey(float f)
{
    unsigned u = __float_as_uint(f);
    return u ^ ((unsigned)((int)u >> 31) | 0x80000000u);
}
__device__ __forceinline__ float funkey(unsigned k)
{
    unsigned u = (k & 0x80000000u) ? (k ^ 0x80000000u) : ~k;
    return __uint_as_float(u);
}

// ---------------- packed f32x2 FMA ----------------
__device__ __forceinline__ float2 ffma2(float2 a, float2 b, float2 c)
{
    unsigned long long au = *reinterpret_cast<unsigned long long*>(&a);
    unsigned long long bu = *reinterpret_cast<unsigned long long*>(&b);
    unsigned long long cu = *reinterpret_cast<unsigned long long*>(&c);
    unsigned long long du;
    asm("fma.rn.f32x2 %0, %1, %2, %3;" : "=l"(du) : "l"(au), "l"(bu), "l"(cu));
    return *reinterpret_cast<float2*>(&du);
}

// ---------------- cp.async helpers ----------------
__device__ __forceinline__ void cp_async16(float* sdst, const float* gsrc)
{
    unsigned saddr = (unsigned)__cvta_generic_to_shared(sdst);
    asm volatile("cp.async.cg.shared.global [%0], [%1], 16;" :: "r"(saddr), "l"(gsrc));
}
#define CP_COMMIT() asm volatile("cp.async.commit_group;" ::: "memory")
#define CP_WAIT0()  asm volatile("cp.async.wait_group 0;" ::: "memory")

// Permute: (s,a,p,c) -> s*200 + a*20 + (c/2)*4 + (c%2)*2 + p.
// Each (s,a) row = 5 aligned float4s of (p0,p1) c-pairs.
__device__ __forceinline__ int wm_perm(int t)
{
    const int s  = t / 200;
    const int r  = t - s * 200;
    const int a  = r / 20;
    const int r2 = r - a * 20;
    const int p  = r2 / 10;
    const int c  = r2 - p * 10;
    return s * 200 + a * 20 + ((c >> 1) << 2) + ((c & 1) << 1) + p;
}

__device__ __forceinline__ void stage_wm_g(const float* __restrict__ gWm,
                                           float* __restrict__ sWm, int tid)
{
    #pragma unroll
    for (int t = tid; t < 1400; t += NT) sWm[wm_perm(t)] = gWm[t];
}
__device__ __forceinline__ void stage_wm_s(const float* __restrict__ sRaw,
                                           float* __restrict__ sWm, int tid)
{
    #pragma unroll
    for (int t = tid; t < 1400; t += NT) sWm[wm_perm(t)] = sRaw[t];
}

// ---------------- single-sample MPS core, lazy sincos ----------------
__device__ __forceinline__ float mps_core(const float* f,
                                          const float* __restrict__ w0c,
                                          const float* __restrict__ w0s,
                                          const float* __restrict__ sWm,
                                          const float* __restrict__ sWn)
{
    float c0, s0;
    __sincosf(f[0] * PI_HALF, &s0, &c0);
    float v[10];
    #pragma unroll
    for (int a = 0; a < 10; a++)
        v[a] = fmaf(s0, w0s[a], c0 * w0c[a]);

    #pragma unroll
    for (int s = 0; s < 7; s++) {
        float cn, sn;                      // MUFU overlapped with the a-loop
        __sincosf(f[s + 1] * PI_HALF, &sn, &cn);
        const float4* M = reinterpret_cast<const float4*>(sWm + s * 200);
        float2 acc[10];
        #pragma unroll
        for (int c = 0; c < 10; c++) acc[c] = make_float2(0.f, 0.f);
        #pragma unroll
        for (int a = 0; a < 10; a++) {
            const float2 va2 = make_float2(v[a], v[a]);
            const float4* Ma = M + a * 5;
            #pragma unroll
            for (int j = 0; j < 5; j++) {
                const float4 m = Ma[j];    // one LDS.128 -> 2 FFMA2
                acc[2 * j]     = ffma2(va2, make_float2(m.x, m.y), acc[2 * j]);
                acc[2 * j + 1] = ffma2(va2, make_float2(m.z, m.w), acc[2 * j + 1]);
            }
        }
        #pragma unroll
        for (int c = 0; c < 10; c++)
            v[c] = fmaf(sn, acc[c].y, cn * acc[c].x);
    }

    float ce, se;
    __sincosf(f[8] * PI_HALF, &se, &ce);
    float r = 0.f;
    #pragma unroll
    for (int a = 0; a < 10; a++)
        r = fmaf(v[a], fmaf(se, sWn[2 * a + 1], ce * sWn[2 * a]), r);
    return r;
}

// ---------------- single fused kernel ----------------
// launch_bounds(128,5): 102-reg cap, grid 5*SMs (=740) -> single-wave phase 0.
__global__ void __launch_bounds__(NT, 5)
fused_lotenet(const float* __restrict__ x,
              const float* __restrict__ W00, const float* __restrict__ Wm0, const float* __restrict__ Wn0,
              const float* __restrict__ W01, const float* __restrict__ Wm1, const float* __restrict__ Wn1,
              const float* __restrict__ W02, const float* __restrict__ Wm2, const float* __restrict__ Wn2,
              const float* __restrict__ W03, const float* __restrict__ Wm3, const float* __restrict__ Wn3,
              float* __restrict__ out)
{
    __shared__ __align__(16) float sWm[1400];
    __shared__ __align__(16) float sRaw[1664];
    __shared__ __align__(16) float sW0[200];
    __shared__ float sWn[20];

    const int tid = threadIdx.x;   // sample b
    const int bid = blockIdx.x;
    const int nblk = gridDim.x;

    float f[9];

    // ---- Phase 0: layer-0 MPS, one pixel per block (single wave, exactly
    //      one pixel per block since grid >= 729). Feature LDGs issued first
    //      so their latency overlaps the weight staging. ----
    if (bid < 729) {
        const int n = bid;
        const int i = n / 27, j = n - i * 27;
        #pragma unroll
        for (int k = 0; k < 9; k++) {
            const int r = 3 * i + k / 3;
            const int c = 3 * j + (k - (k / 3) * 3);
            f[k] = x[((size_t)tid * 81 + r) * 81 + c];
        }
        stage_wm_g(Wm0 + n * 1400, sWm, tid);
        if (tid < 20)      sW0[tid]      = W00[n * 20 + tid];
        else if (tid < 40) sWn[tid - 20] = Wn0[n * 20 + (tid - 20)];
        __syncthreads();

        const float y = mps_core(f, sW0, sW0 + 10, sWm, sWn);
        g_y0[n * 128 + tid] = y;
        atomicMax(&g_kx0[tid * 32], fkey(y));
        atomicMax(&g_kn0[tid * 32], ~fkey(y));
    }

    // Prefetch phase-1 weights; copies land while we spin in the barrier.
    if (bid < 81) {
        const float* gWm = Wm1 + bid * 1400;
        const float* gW0 = W01 + bid * 20;
        const float* gWn = Wn1 + bid * 20;
        #pragma unroll
        for (int t = tid; t < 360; t += NT) {
            if (t < 350)      cp_async16(sRaw + t * 4,                gWm + t * 4);
            else if (t < 355) cp_async16(sRaw + 1400 + (t - 350) * 4, gW0 + (t - 350) * 4);
            else              cp_async16(sRaw + 1420 + (t - 355) * 4, gWn + (t - 355) * 4);
        }
        CP_COMMIT();
    }
    grid_barrier();

    // ---- Phase 1: layer-1 MPS, 81 blocks ----
    if (bid < 81) {
        CP_WAIT0();
        __syncthreads();
        stage_wm_s(sRaw, sWm, tid);
        if (tid < 20)      sW0[tid]      = sRaw[1400 + tid];
        else if (tid < 40) sWn[tid - 20] = sRaw[1420 + (tid - 20)];

        const float mn = funkey(~g_kn0[tid * 32]);
        const float iv = 1.0f / (funkey(g_kx0[tid * 32]) - mn);
        __syncthreads();

        const int n = bid;
        const int i = n / 9, j = n - i * 9;
        #pragma unroll
        for (int k = 0; k < 9; k++) {
            const int r = 3 * i + k / 3;
            const int c = 3 * j + (k - (k / 3) * 3);
            f[k] = (g_y0[(r * 27 + c) * 128 + tid] - mn) * iv;
        }
        const float y = mps_core(f, sW0, sW0 + 10, sWm, sWn);
        g_y1[n * 128 + tid] = y;
        atomicMax(&g_kx1[tid * 32], fkey(y));
        atomicMax(&g_kn1[tid * 32], ~fkey(y));

        // Prefetch phase-2 weights (blocks 0..8).
        if (bid < 9) {
            __syncthreads();
            const float* gWm = Wm2 + bid * 1400;
            const float* gW0 = W02 + bid * 20;
            const float* gWn = Wn2 + bid * 20;
            #pragma unroll
            for (int t = tid; t < 360; t += NT) {
                if (t < 350)      cp_async16(sRaw + t * 4,                gWm + t * 4);
                else if (t < 355) cp_async16(sRaw + 1400 + (t - 350) * 4, gW0 + (t - 350) * 4);
                else              cp_async16(sRaw + 1420 + (t - 355) * 4, gWn + (t - 355) * 4);
            }
            CP_COMMIT();
        }
    }
    grid_barrier();

    // ---- Phase 2: layer-2 MPS, 9 blocks. Last block resets L0 keys. ----
    if (bid < 9) {
        CP_WAIT0();
        __syncthreads();
        stage_wm_s(sRaw, sWm, tid);
        if (tid < 20)      sW0[tid]      = sRaw[1400 + tid];
        else if (tid < 40) sWn[tid - 20] = sRaw[1420 + (tid - 20)];

        const float mn = funkey(~g_kn1[tid * 32]);
        const float iv = 1.0f / (funkey(g_kx1[tid * 32]) - mn);
        __syncthreads();

        const int n = bid;
        const int i = n / 3, j = n - i * 3;
        #pragma unroll
        for (int k = 0; k < 9; k++) {
            const int r = 3 * i + k / 3;
            const int c = 3 * j + (k - (k / 3) * 3);
            f[k] = (g_y1[(r * 9 + c) * 128 + tid] - mn) * iv;
        }
        g_y2[n * 128 + tid] = mps_core(f, sW0, sW0 + 10, sWm, sWn);
    } else if (bid == nblk - 1) {
        g_kx0[tid * 32] = 0;
        g_kn0[tid * 32] = 0;
    }
    // Prefetch final-layer weights (blocks 0..9).
    if (bid < 10) {
        if (bid < 9) __syncthreads();
        #pragma unroll
        for (int t = tid; t < 405; t += NT) {
            if (t < 350)      cp_async16(sRaw + t * 4,                Wm3 + t * 4);
            else if (t < 400) cp_async16(sRaw + 1400 + (t - 350) * 4, W03 + (t - 350) * 4);
            else              cp_async16(sRaw + 1600 + (t - 400) * 4, Wn3 + (t - 400) * 4);
        }
        CP_COMMIT();
    }
    grid_barrier();

    // ---- Phase 3: final MPS (O=10), 10 blocks. Last block resets L1 keys. ----
    if (bid < 10) {
        CP_WAIT0();
        __syncthreads();
        stage_wm_s(sRaw, sWm, tid);
        #pragma unroll
        for (int t = tid; t < 200; t += NT) sW0[t] = sRaw[1400 + t];
        if (tid < 20) sWn[tid] = sRaw[1600 + tid];

        float yk[9];
        float mn = INFINITY, mx = -INFINITY;
        #pragma unroll
        for (int k = 0; k < 9; k++) {
            yk[k] = g_y2[k * 128 + tid];
            mn = fminf(mn, yk[k]);
            mx = fmaxf(mx, yk[k]);
        }
        const float iv = 1.0f / (mx - mn);
        __syncthreads();

        #pragma unroll
        for (int k = 0; k < 9; k++) f[k] = (yk[k] - mn) * iv;

        const int o = bid;
        out[tid * 10 + o] = mps_core(f, sW0 + o * 10, sW0 + 100 + o * 10, sWm, sWn);
    } else if (bid == nblk - 1) {
        g_kx1[tid * 32] = 0;
        g_kn1[tid * 32] = 0;
    }
}

extern "C" void kernel_launch(void* const* d_in, const int* in_sizes, int n_in,
                              void* d_out, int out_size)
{
    const float* x   = (const float*)d_in[0];
    const float* W00 = (const float*)d_in[1];
    const float* Wm0 = (const float*)d_in[2];
    const float* Wn0 = (const float*)d_in[3];
    const float* W01 = (const float*)d_in[6];
    const float* Wm1 = (const float*)d_in[7];
    const float* Wn1 = (const float*)d_in[8];
    const float* W02 = (const float*)d_in[11];
    const float* Wm2 = (const float*)d_in[12];
    const float* Wn2 = (const float*)d_in[13];
    const float* W03 = (const float*)d_in[16];
    const float* Wm3 = (const float*)d_in[17];
    const float* Wn3 = (const float*)d_in[18];

    int nsm = 148;
    cudaDeviceGetAttribute(&nsm, cudaDevAttrMultiProcessorCount, 0);
    const int grid = 5 * nsm;   // __launch_bounds__(128,5): all resident

    fused_lotenet<<<grid, NT>>>(x, W00, Wm0, Wn0, W01, Wm1, Wn1,
                                W02, Wm2, Wn2, W03, Wm3, Wn3,
                                (float*)d_out);
}